// round 1
// baseline (speedup 1.0000x reference)
#include <cuda_runtime.h>

#define N_NODES 50000
#define N_EDGES 800000
#define IN_F    128
#define HEADS   4
#define OUT_F   32
#define HO      128            // HEADS*OUT_F
#define NEG_SLOPE 0.2f
#define EPS     1e-10f
#define NB      4              // nodes per block-iteration in projection

// ---------------- scratch (device globals; no dynamic allocation) ----------
__device__ float g_h[N_NODES * HO];          // projected features [N, H*O]
__device__ float g_esrc[N_NODES * HEADS];    // per-node src logits
__device__ float g_edst[N_NODES * HEADS];    // per-node dst logits
__device__ int   g_emax[N_NODES * HEADS];    // float bits, init 0 (= clamp at 0.0f)
__device__ float g_sumexp[N_NODES * HEADS];  // softmax denominators (unnormalized)
__device__ float g_ebuf[N_EDGES * HEADS];    // leaky-relu'd edge logits

// ---------------- K0: zero out + scratch ------------------------------------
__global__ void k0_zero(float* __restrict__ out) {
    int tid = blockIdx.x * blockDim.x + threadIdx.x;
    if (tid < N_NODES * HO) out[tid] = 0.0f;
    if (tid < N_NODES * HEADS) {
        g_emax[tid] = 0;          // 0x0 == 0.0f bits -> seg-max clamped at 0
        g_sumexp[tid] = 0.0f;
    }
}

// ---------------- K1: projection + node logits ------------------------------
// h[n, head*32+o] = sum_i x[n,i] * W[head,i,o]
// e_src[n,head]   = sum_o h[n,head,o] * a_src[head,o]   (likewise e_dst)
// Block: 128 threads (warp == head). W, a_src, a_dst, x-rows in smem.
__global__ void k1_project(const float* __restrict__ x,
                           const float* __restrict__ W,
                           const float* __restrict__ a_src,
                           const float* __restrict__ a_dst) {
    extern __shared__ float sm[];
    float* sW = sm;              // 16384 floats  (W as [head][i][o])
    float* sA = sm + 16384;      // 128 floats    (a_src flattened [head][o])
    float* sB = sm + 16512;      // 128 floats    (a_dst)
    float* sx = sm + 16640;      // NB*128 floats (x rows)

    const int t    = threadIdx.x;     // 0..127
    const int head = t >> 5;
    const int lane = t & 31;

    // Load W into smem (float4, 32 iters of 128 threads)
    {
        const float4* W4 = (const float4*)W;
        float4* sW4 = (float4*)sW;
        #pragma unroll
        for (int k = 0; k < 32; k++) sW4[k * 128 + t] = W4[k * 128 + t];
        sA[t] = a_src[t];
        sB[t] = a_dst[t];
    }
    __syncthreads();

    const float as = sA[t];
    const float ad = sB[t];
    const float* Wcol = sW + head * (IN_F * OUT_F) + lane;   // stride 32 over i

    for (int base = blockIdx.x * NB; base < N_NODES; base += gridDim.x * NB) {
        __syncthreads();
        // load NB rows of x (float4): thread t loads row base + t/32, chunk t%32
        {
            int j = t >> 5;
            int q = t & 31;
            int n = base + j;
            float4 v = make_float4(0.f, 0.f, 0.f, 0.f);
            if (n < N_NODES) v = ((const float4*)x)[n * (IN_F / 4) + q];
            ((float4*)sx)[j * (IN_F / 4) + q] = v;
        }
        __syncthreads();

        float acc0 = 0.f, acc1 = 0.f, acc2 = 0.f, acc3 = 0.f;
        #pragma unroll 8
        for (int i = 0; i < IN_F; i++) {
            float w = Wcol[i * OUT_F];
            acc0 += w * sx[0 * IN_F + i];
            acc1 += w * sx[1 * IN_F + i];
            acc2 += w * sx[2 * IN_F + i];
            acc3 += w * sx[3 * IN_F + i];
        }

        float acc[NB] = {acc0, acc1, acc2, acc3};
        #pragma unroll
        for (int j = 0; j < NB; j++) {
            int n = base + j;
            if (n < N_NODES) g_h[n * HO + t] = acc[j];
            // warp reduce for logits (warp == one head, 32 outputs)
            float s = acc[j] * as;
            float d = acc[j] * ad;
            #pragma unroll
            for (int off = 16; off; off >>= 1) {
                s += __shfl_xor_sync(0xFFFFFFFFu, s, off);
                d += __shfl_xor_sync(0xFFFFFFFFu, d, off);
            }
            if (lane == 0 && n < N_NODES) {
                g_esrc[n * HEADS + head] = s;
                g_edst[n * HEADS + head] = d;
            }
        }
    }
}

// ---------------- K2: edge logits (leaky relu) + segment max -----------------
__global__ void k2_edge_logits(const int* __restrict__ ei) {
    int tid = blockIdx.x * blockDim.x + threadIdx.x;
    if (tid >= N_EDGES * HEADS) return;
    int e  = tid >> 2;
    int hd = tid & 3;
    int src = ei[e];
    int dst = ei[N_EDGES + e];
    float v = g_esrc[src * HEADS + hd] + g_edst[dst * HEADS + hd];
    v = (v >= 0.f) ? v : NEG_SLOPE * v;
    g_ebuf[tid] = v;
    // int-ordered atomicMax: valid because buffer init is 0 (>= any negative's
    // int bits) and positive float ordering == positive int ordering.
    atomicMax(&g_emax[dst * HEADS + hd], __float_as_int(v));
}

// ---------------- K3: fused exp + weighted scatter-add -----------------------
// out[dst, :] += exp(e - emax[dst]) * h[src, :]   ;   sumexp[dst,h] += exp(...)
__global__ void k3_scatter(const int* __restrict__ ei, float* __restrict__ out) {
    const int t  = threadIdx.x;      // 0..127
    const int hd = t >> 5;
    for (int e = blockIdx.x; e < N_EDGES; e += gridDim.x) {
        int src = ei[e];
        int dst = ei[N_EDGES + e];
        float emax = __int_as_float(g_emax[dst * HEADS + hd]);
        float ev   = g_ebuf[e * HEADS + hd];
        float ex   = __expf(ev - emax);
        if ((t & 31) == 0) atomicAdd(&g_sumexp[dst * HEADS + hd], ex);
        atomicAdd(&out[dst * HO + t], ex * g_h[src * HO + t]);
    }
}

// ---------------- K4: normalize ----------------------------------------------
__global__ void k4_norm(float* __restrict__ out) {
    int tid = blockIdx.x * blockDim.x + threadIdx.x;
    if (tid >= N_NODES * HO) return;
    int n  = tid >> 7;
    int hd = (tid >> 5) & 3;
    out[tid] = out[tid] / (g_sumexp[n * HEADS + hd] + EPS);
}

// ---------------- launch ------------------------------------------------------
extern "C" void kernel_launch(void* const* d_in, const int* in_sizes, int n_in,
                              void* d_out, int out_size) {
    const float* x     = (const float*)d_in[0];
    const int*   ei    = (const int*)d_in[1];
    const float* W     = (const float*)d_in[2];
    const float* a_src = (const float*)d_in[3];
    const float* a_dst = (const float*)d_in[4];
    float* out = (float*)d_out;

    // K0: zero output + scratch
    {
        int n = N_NODES * HO;
        k0_zero<<<(n + 255) / 256, 256>>>(out);
    }

    // K1: projection. 68608 B dynamic smem -> need attribute bump (>48KB).
    {
        static bool attr_set = false;
        size_t smem = (16384 + 128 + 128 + NB * IN_F) * sizeof(float);
        if (!attr_set) {
            cudaFuncSetAttribute(k1_project,
                                 cudaFuncAttributeMaxDynamicSharedMemorySize,
                                 (int)smem);
            attr_set = true;
        }
        k1_project<<<444, 128, smem>>>(x, W, a_src, a_dst);
    }

    // K2: edge logits + segment max
    {
        int n = N_EDGES * HEADS;
        k2_edge_logits<<<(n + 255) / 256, 256>>>(ei);
    }

    // K3: fused exp + scatter
    k3_scatter<<<9472, 128>>>(ei, out);

    // K4: normalize
    {
        int n = N_NODES * HO;
        k4_norm<<<(n + 255) / 256, 256>>>(out);
    }
}

// round 2
// speedup vs baseline: 2.0343x; 2.0343x over previous
#include <cuda_runtime.h>

#define N_NODES 50000
#define N_EDGES 800000
#define IN_F    128
#define HEADS   4
#define OUT_F   32
#define HO      128            // HEADS*OUT_F
#define NEG_SLOPE 0.2f
#define EPS     1e-10f
#define NB      4              // nodes per block-iteration in projection

#define SB      512                        // scan block size
#define NSCANB  ((N_NODES + SB - 1) / SB)  // 98

// ---------------- scratch (device globals; no dynamic allocation) ----------
__device__ float g_h[N_NODES * HO];          // projected features [N, H*O]
__device__ float g_esrc[N_NODES * HEADS];    // per-node src logits
__device__ float g_edst[N_NODES * HEADS];    // per-node dst logits
__device__ int   g_count[N_NODES];           // in-degree histogram
__device__ int   g_cursor[N_NODES];          // scatter cursors
__device__ int   g_row[N_NODES + 1];         // CSR row offsets
__device__ int   g_bsum[NSCANB];             // scan partials
__device__ int   g_boff[NSCANB];             // scanned block offsets
__device__ int   g_srcidx[N_EDGES];          // src node per CSR slot
__device__ float g_eval[N_EDGES * HEADS];    // leaky-relu'd edge logits, CSR order

// ---------------- K0: zero histogram + cursors -------------------------------
__global__ void k0_zero() {
    int tid = blockIdx.x * blockDim.x + threadIdx.x;
    if (tid < N_NODES) { g_count[tid] = 0; g_cursor[tid] = 0; }
}

// ---------------- K1: projection + node logits ------------------------------
__global__ void k1_project(const float* __restrict__ x,
                           const float* __restrict__ W,
                           const float* __restrict__ a_src,
                           const float* __restrict__ a_dst) {
    extern __shared__ float sm[];
    float* sW = sm;              // 16384 floats  (W as [head][i][o])
    float* sA = sm + 16384;      // 128
    float* sB = sm + 16512;      // 128
    float* sx = sm + 16640;      // NB*128

    const int t    = threadIdx.x;     // 0..127
    const int head = t >> 5;
    const int lane = t & 31;

    {
        const float4* W4 = (const float4*)W;
        float4* sW4 = (float4*)sW;
        #pragma unroll
        for (int k = 0; k < 32; k++) sW4[k * 128 + t] = W4[k * 128 + t];
        sA[t] = a_src[t];
        sB[t] = a_dst[t];
    }
    __syncthreads();

    const float as = sA[t];
    const float ad = sB[t];
    const float* Wcol = sW + head * (IN_F * OUT_F) + lane;

    for (int base = blockIdx.x * NB; base < N_NODES; base += gridDim.x * NB) {
        __syncthreads();
        {
            int j = t >> 5;
            int q = t & 31;
            int n = base + j;
            float4 v = make_float4(0.f, 0.f, 0.f, 0.f);
            if (n < N_NODES) v = ((const float4*)x)[n * (IN_F / 4) + q];
            ((float4*)sx)[j * (IN_F / 4) + q] = v;
        }
        __syncthreads();

        float acc0 = 0.f, acc1 = 0.f, acc2 = 0.f, acc3 = 0.f;
        #pragma unroll 8
        for (int i = 0; i < IN_F; i++) {
            float w = Wcol[i * OUT_F];
            acc0 += w * sx[0 * IN_F + i];
            acc1 += w * sx[1 * IN_F + i];
            acc2 += w * sx[2 * IN_F + i];
            acc3 += w * sx[3 * IN_F + i];
        }

        float acc[NB] = {acc0, acc1, acc2, acc3};
        #pragma unroll
        for (int j = 0; j < NB; j++) {
            int n = base + j;
            if (n < N_NODES) g_h[n * HO + t] = acc[j];
            float s = acc[j] * as;
            float d = acc[j] * ad;
            #pragma unroll
            for (int off = 16; off; off >>= 1) {
                s += __shfl_xor_sync(0xFFFFFFFFu, s, off);
                d += __shfl_xor_sync(0xFFFFFFFFu, d, off);
            }
            if (lane == 0 && n < N_NODES) {
                g_esrc[n * HEADS + head] = s;
                g_edst[n * HEADS + head] = d;
            }
        }
    }
}

// ---------------- K2a: in-degree histogram -----------------------------------
__global__ void k2_hist(const int* __restrict__ ei) {
    int e = blockIdx.x * blockDim.x + threadIdx.x;
    if (e < N_EDGES) atomicAdd(&g_count[ei[N_EDGES + e]], 1);
}

// ---------------- scan (3 kernels) -------------------------------------------
__global__ void k_scanA() {
    __shared__ int s[SB];
    int t = threadIdx.x;
    int g = blockIdx.x * SB + t;
    int v = (g < N_NODES) ? g_count[g] : 0;
    s[t] = v;
    __syncthreads();
    for (int off = 1; off < SB; off <<= 1) {
        int add = (t >= off) ? s[t - off] : 0;
        __syncthreads();
        s[t] += add;
        __syncthreads();
    }
    if (g < N_NODES) g_row[g] = s[t] - v;          // exclusive
    if (t == SB - 1) g_bsum[blockIdx.x] = s[t];
}

__global__ void k_scanB() {
    __shared__ int s[128];
    int t = threadIdx.x;
    int v = (t < NSCANB) ? g_bsum[t] : 0;
    s[t] = v;
    __syncthreads();
    for (int off = 1; off < 128; off <<= 1) {
        int add = (t >= off) ? s[t - off] : 0;
        __syncthreads();
        s[t] += add;
        __syncthreads();
    }
    if (t < NSCANB) g_boff[t] = s[t] - v;          // exclusive
}

__global__ void k_scanC() {
    int t = threadIdx.x;
    int g = blockIdx.x * SB + t;
    if (g < N_NODES) g_row[g] += g_boff[blockIdx.x];
    if (g == 0) g_row[N_NODES] = N_EDGES;
}

// ---------------- K2b: scatter edges into CSR + edge logits -----------------
__global__ void k2_scatter(const int* __restrict__ ei) {
    int e = blockIdx.x * blockDim.x + threadIdx.x;
    if (e >= N_EDGES) return;
    int src = ei[e];
    int dst = ei[N_EDGES + e];
    int pos = g_row[dst] + atomicAdd(&g_cursor[dst], 1);
    g_srcidx[pos] = src;
    float4 s = ((const float4*)g_esrc)[src];
    float4 d = ((const float4*)g_edst)[dst];
    float4 v;
    v.x = s.x + d.x; v.x = (v.x >= 0.f) ? v.x : NEG_SLOPE * v.x;
    v.y = s.y + d.y; v.y = (v.y >= 0.f) ? v.y : NEG_SLOPE * v.y;
    v.z = s.z + d.z; v.z = (v.z >= 0.f) ? v.z : NEG_SLOPE * v.z;
    v.w = s.w + d.w; v.w = (v.w >= 0.f) ? v.w : NEG_SLOPE * v.w;
    ((float4*)g_eval)[pos] = v;
}

// ---------------- K3: warp-per-node aggregation (no atomics) -----------------
// lane layout for accumulate: head = lane>>3, quad = lane&7 (4 out feats each)
__global__ void k3_agg(float* __restrict__ out) {
    int warp = (blockIdx.x * blockDim.x + threadIdx.x) >> 5;
    if (warp >= N_NODES) return;
    const int lane = threadIdx.x & 31;
    const int head = lane >> 3;
    const int quad = lane & 7;

    const int start = g_row[warp];
    const int end   = g_row[warp + 1];

    // ---- pass 1: per-head max, clamped below at 0 (matches reference) ----
    // lanes act as 8 edges x 4 heads
    float m = 0.f;
    for (int i0 = start; i0 < end; i0 += 8) {
        int e = i0 + (lane >> 2);
        float v = (e < end) ? g_eval[e * HEADS + (lane & 3)] : 0.f;
        m = fmaxf(m, v);
    }
    m = fmaxf(m, __shfl_xor_sync(0xFFFFFFFFu, m, 4));
    m = fmaxf(m, __shfl_xor_sync(0xFFFFFFFFu, m, 8));
    m = fmaxf(m, __shfl_xor_sync(0xFFFFFFFFu, m, 16));
    m = __shfl_sync(0xFFFFFFFFu, m, head);   // lane h in 0..3 holds head h's max

    // ---- pass 2: accumulate exp-weighted features ----
    float4 acc = make_float4(0.f, 0.f, 0.f, 0.f);
    float ssum = 0.f;
    #pragma unroll 4
    for (int i = start; i < end; i++) {
        int src = g_srcidx[i];
        float ev = g_eval[i * HEADS + head];
        float ex = __expf(ev - m);
        float4 hv = ((const float4*)g_h)[src * 32 + lane];
        acc.x += ex * hv.x;
        acc.y += ex * hv.y;
        acc.z += ex * hv.z;
        acc.w += ex * hv.w;
        if (quad == 0) ssum += ex;
    }
    ssum = __shfl_sync(0xFFFFFFFFu, ssum, head << 3);
    float inv = 1.f / (ssum + EPS);
    acc.x *= inv; acc.y *= inv; acc.z *= inv; acc.w *= inv;
    ((float4*)out)[warp * 32 + lane] = acc;
}

// ---------------- launch ------------------------------------------------------
extern "C" void kernel_launch(void* const* d_in, const int* in_sizes, int n_in,
                              void* d_out, int out_size) {
    const float* x     = (const float*)d_in[0];
    const int*   ei    = (const int*)d_in[1];
    const float* W     = (const float*)d_in[2];
    const float* a_src = (const float*)d_in[3];
    const float* a_dst = (const float*)d_in[4];
    float* out = (float*)d_out;

    k0_zero<<<(N_NODES + 255) / 256, 256>>>();

    {
        static bool attr_set = false;
        size_t smem = (16384 + 128 + 128 + NB * IN_F) * sizeof(float);
        if (!attr_set) {
            cudaFuncSetAttribute(k1_project,
                                 cudaFuncAttributeMaxDynamicSharedMemorySize,
                                 (int)smem);
            attr_set = true;
        }
        k1_project<<<444, 128, smem>>>(x, W, a_src, a_dst);
    }

    k2_hist<<<(N_EDGES + 255) / 256, 256>>>(ei);
    k_scanA<<<NSCANB, SB>>>();
    k_scanB<<<1, 128>>>();
    k_scanC<<<NSCANB, SB>>>();
    k2_scatter<<<(N_EDGES + 255) / 256, 256>>>(ei);

    // warp per node: 256 threads = 8 warps/block
    k3_agg<<<(N_NODES * 32 + 255) / 256, 256>>>(out);
}